// round 4
// baseline (speedup 1.0000x reference)
#include <cuda_runtime.h>
#include <math.h>

#define DEVFN __device__ __forceinline__

constexpr int C    = 128;
constexpr int C3   = 384;
constexpr int HIMG = 256;
constexpr int WIMG = 256;
constexpr int NPIX = HIMG * WIMG;   // 65536
constexpr int HD   = 8;
constexpr int CH   = 16;            // channels per head

// ---------------- scratch arena (single batch at a time) --------------------
// [0 .. 25165824)        : qkv conv1x1 output (384*65536)  -- later reused as z
// [25165824 .. 50331648) : dwconv'd q|k|v (each 128*65536)
constexpr size_t OFF_QKV  = 0;
constexpr size_t OFF_QKVD = (size_t)C3 * NPIX;
constexpr size_t OFF_Q    = OFF_QKVD;
constexpr size_t OFF_K    = OFF_QKVD + (size_t)C * NPIX;
constexpr size_t OFF_V    = OFF_QKVD + (size_t)2 * C * NPIX;
constexpr size_t OFF_Z    = 0;   // aliases qkv region (dead after dw_split)

__device__ float g_scratch[(size_t)2 * C3 * NPIX];   // 201.3 MB
__device__ float g_sa[NPIX];                          // per-batch gate
__device__ float g_ssq_q[C];
__device__ float g_ssq_k[C];
__device__ float g_vsum[C];
__device__ float g_S[HD * CH * CH];
__device__ float g_attn[HD * CH * CH];
__device__ float g_spec[C];

// ---------------- f32x2 packed-FMA helpers (Blackwell FFMA2) ----------------
DEVFN unsigned long long dup2(float v) {
    unsigned long long r;
    asm("mov.b64 %0, {%1, %1};" : "=l"(r) : "f"(v));
    return r;
}
DEVFN void fma2(unsigned long long &c, unsigned long long a, unsigned long long b) {
    asm("fma.rn.f32x2 %0, %1, %2, %0;" : "+l"(c) : "l"(a), "l"(b));
}
DEVFN void upk2(unsigned long long v, float &lo, float &hi) {
    asm("mov.b64 {%0, %1}, %2;" : "=f"(lo), "=f"(hi) : "l"(v));
}

DEVFN float gelu_exact(float x) {
    return 0.5f * x * (1.0f + erff(x * 0.70710678118654752440f));
}

// ---------------- init: zero the small atomic accumulators ------------------
__global__ void init_kernel() {
    int tid = threadIdx.x;
    for (int i = tid; i < C; i += 256) { g_ssq_q[i] = 0.f; g_ssq_k[i] = 0.f; g_vsum[i] = 0.f; }
    for (int i = tid; i < HD * CH * CH; i += 256) g_S[i] = 0.f;
}

// ---------------- spatial-attention gate: sa[n] from y[b] -------------------
__global__ __launch_bounds__(256)
void sa_kernel(const float* __restrict__ yb,
               const float* __restrict__ w1,   // [16][128]
               const float* __restrict__ w2,   // [16][16]
               const float* __restrict__ w3)   // [16]
{
    __shared__ float w1s[16][128];
    __shared__ float w2s[16][16];
    __shared__ float w3s[16];
    int tid = threadIdx.x;
    for (int i = tid; i < 16 * 128; i += 256) w1s[i >> 7][i & 127] = w1[i];
    w2s[tid >> 4][tid & 15] = w2[tid];
    if (tid < 16) w3s[tid] = w3[tid];
    __syncthreads();

    int n = blockIdx.x * 256 + tid;
    const float* yp = yb + n;

    float t1[16];
#pragma unroll
    for (int j = 0; j < 16; ++j) t1[j] = 0.f;
    for (int ic = 0; ic < C; ic += 4) {
        float y0 = yp[(size_t)(ic + 0) * NPIX];
        float y1 = yp[(size_t)(ic + 1) * NPIX];
        float y2 = yp[(size_t)(ic + 2) * NPIX];
        float y3 = yp[(size_t)(ic + 3) * NPIX];
#pragma unroll
        for (int j = 0; j < 16; ++j)
            t1[j] += w1s[j][ic] * y0 + w1s[j][ic + 1] * y1
                   + w1s[j][ic + 2] * y2 + w1s[j][ic + 3] * y3;
    }
    float t2[16];
#pragma unroll
    for (int j = 0; j < 16; ++j) {
        float a = 0.f;
#pragma unroll
        for (int i = 0; i < 16; ++i) a += fmaxf(t1[i], 0.f) * w2s[j][i];
        t2[j] = fmaxf(a, 0.f);
    }
    float s3 = 0.f;
#pragma unroll
    for (int i = 0; i < 16; ++i) s3 += t2[i] * w3s[i];
    g_sa[n] = 1.f / (1.f + expf(-s3));
}

// ---------------- conv1x1 GEMM: OUT[oc,n] = sum_ic W[oc,ic]*X[ic,n] ---------
// Block tile: 64 oc x 128 n. Thread: 8 oc (4 packed pairs) x 4 n, FFMA2 core.
DEVFN void conv1x1_body(const float* __restrict__ Wt,
                        const float* __restrict__ X,
                        float* __restrict__ OUT)
{
    __shared__ __align__(16) float xs[16][128];
    __shared__ __align__(16) float ws[16][66];
    const int tid    = threadIdx.x;
    const int nbase  = blockIdx.x * 128;
    const int ocbase = blockIdx.y * 64;
    const int lane = tid & 31;
    const int wrp  = tid >> 5;
    const int n0   = lane * 4;
    const int oc0  = wrp * 8;

    unsigned long long acc[4][4];
#pragma unroll
    for (int i = 0; i < 4; ++i)
#pragma unroll
        for (int j = 0; j < 4; ++j) acc[i][j] = 0ull;

    const float* Xb = X + nbase;
    for (int ic0 = 0; ic0 < C; ic0 += 16) {
#pragma unroll
        for (int i = 0; i < 2; ++i) {
            int idx = tid + i * 256;
            int r = idx >> 5, c4 = (idx & 31) << 2;
            *(float4*)&xs[r][c4] =
                *(const float4*)&Xb[(size_t)(ic0 + r) * NPIX + c4];
        }
        {
            int oc = tid >> 2, kk0 = (tid & 3) << 2;
            float4 wv = *(const float4*)&Wt[(size_t)(ocbase + oc) * C + ic0 + kk0];
            ws[kk0 + 0][oc] = wv.x;
            ws[kk0 + 1][oc] = wv.y;
            ws[kk0 + 2][oc] = wv.z;
            ws[kk0 + 3][oc] = wv.w;
        }
        __syncthreads();
#pragma unroll
        for (int kk = 0; kk < 16; ++kk) {
            float4 xv = *(const float4*)&xs[kk][n0];
            unsigned long long xd[4];
            xd[0] = dup2(xv.x); xd[1] = dup2(xv.y);
            xd[2] = dup2(xv.z); xd[3] = dup2(xv.w);
            unsigned long long wp[4];
#pragma unroll
            for (int i = 0; i < 4; ++i)
                wp[i] = *(const unsigned long long*)&ws[kk][oc0 + 2 * i];
#pragma unroll
            for (int i = 0; i < 4; ++i)
#pragma unroll
                for (int j = 0; j < 4; ++j)
                    fma2(acc[i][j], wp[i], xd[j]);
        }
        __syncthreads();
    }
    float* Ob = OUT + nbase;
#pragma unroll
    for (int i = 0; i < 4; ++i) {
        float lo[4], hi[4];
#pragma unroll
        for (int j = 0; j < 4; ++j) upk2(acc[i][j], lo[j], hi[j]);
        *(float4*)&Ob[(size_t)(ocbase + oc0 + 2 * i) * NPIX + n0] =
            make_float4(lo[0], lo[1], lo[2], lo[3]);
        *(float4*)&Ob[(size_t)(ocbase + oc0 + 2 * i + 1) * NPIX + n0] =
            make_float4(hi[0], hi[1], hi[2], hi[3]);
    }
}

__global__ __launch_bounds__(256, 4)
void qkv_conv_kernel(const float* __restrict__ Wt, const float* __restrict__ X) {
    conv1x1_body(Wt, X, g_scratch + OFF_QKV);
}
__global__ __launch_bounds__(256, 4)
void proj_conv_kernel(const float* __restrict__ Wt, float* __restrict__ OUT) {
    conv1x1_body(Wt, g_scratch + OFF_Z, OUT);
}

// ---------------- dwconv3x3 + split + sa-gate + norm/vsum accumulation ------
// grid: (W/32, H/8, C3), block 256 = 32x8 pixel tile
__global__ __launch_bounds__(256)
void dw_split_kernel(const float* __restrict__ qkv_dw_w)
{
    __shared__ float s[10][34];
    __shared__ float wloc[9];
    __shared__ float red[8];
    int ch = blockIdx.z;
    int x0 = blockIdx.x * 32, yy0 = blockIdx.y * 8;
    int tid = threadIdx.x;
    const float* src = g_scratch + OFF_QKV + (size_t)ch * NPIX;
    if (tid < 9) wloc[tid] = qkv_dw_w[ch * 9 + tid];
    for (int i = tid; i < 340; i += 256) {
        int hy = i / 34, hx = i % 34;
        int gy = yy0 - 1 + hy, gx = x0 - 1 + hx;
        float v = 0.f;
        if ((unsigned)gy < 256u && (unsigned)gx < 256u) v = src[gy * 256 + gx];
        s[hy][hx] = v;
    }
    __syncthreads();
    int tx = tid & 31, ty = tid >> 5;
    float a = 0.f;
#pragma unroll
    for (int dy = 0; dy < 3; ++dy)
#pragma unroll
        for (int dx = 0; dx < 3; ++dx)
            a += s[ty + dy][tx + dx] * wloc[dy * 3 + dx];
    int n = (yy0 + ty) * 256 + x0 + tx;

    float contrib;
    float* tgt;
    if (ch < C) {
        float val = a * g_sa[n];
        g_scratch[OFF_Q + (size_t)ch * NPIX + n] = val;
        contrib = val * val;
        tgt = &g_ssq_q[ch];
    } else if (ch < 2 * C) {
        int c = ch - C;
        g_scratch[OFF_K + (size_t)c * NPIX + n] = a;
        contrib = a * a;
        tgt = &g_ssq_k[c];
    } else {
        int c = ch - 2 * C;
        g_scratch[OFF_V + (size_t)c * NPIX + n] = a;
        contrib = a;
        tgt = &g_vsum[c];
    }

    for (int o = 16; o; o >>= 1) contrib += __shfl_xor_sync(0xffffffffu, contrib, o);
    if ((tid & 31) == 0) red[tid >> 5] = contrib;
    __syncthreads();
    if (tid == 0) {
        float t = 0.f;
#pragma unroll
        for (int i = 0; i < 8; ++i) t += red[i];
        atomicAdd(tgt, t);
    }
}

// ---------------- Gram: S[h,c,d] = sum_n q[c,n]*k[d,n] ----------------------
// grid: (16 n-chunks, 8 heads), block 256
__global__ __launch_bounds__(256)
void gram_kernel()
{
    __shared__ float qs[16][257];
    __shared__ float ks[16][257];
    int h = blockIdx.y;
    const float* qb = g_scratch + OFF_Q + (size_t)h * CH * NPIX;
    const float* kb = g_scratch + OFF_K + (size_t)h * CH * NPIX;
    int n0 = blockIdx.x * 4096;
    int tid = threadIdx.x;
    int slice = tid >> 6;
    int r = tid & 63;
    int c0 = (r >> 3) * 2;
    int d0 = (r & 7) * 2;
    float acc00 = 0.f, acc01 = 0.f, acc10 = 0.f, acc11 = 0.f;

    for (int it = 0; it < 16; ++it) {
        int nb = n0 + it * 256;
        for (int i = tid; i < 16 * 256; i += 256) {
            int rr = i >> 8, cc = i & 255;
            qs[rr][cc] = qb[(size_t)rr * NPIX + nb + cc];
            ks[rr][cc] = kb[(size_t)rr * NPIX + nb + cc];
        }
        __syncthreads();
        int base = slice * 64;
#pragma unroll 4
        for (int nn = 0; nn < 64; ++nn) {
            int m = base + nn;
            float q0 = qs[c0][m], q1 = qs[c0 + 1][m];
            float k0 = ks[d0][m], k1 = ks[d0 + 1][m];
            acc00 += q0 * k0; acc01 += q0 * k1;
            acc10 += q1 * k0; acc11 += q1 * k1;
        }
        __syncthreads();
    }
    float* Sb = g_S + (size_t)h * CH * CH;
    atomicAdd(&Sb[(c0    ) * CH + d0    ], acc00);
    atomicAdd(&Sb[(c0    ) * CH + d0 + 1], acc01);
    atomicAdd(&Sb[(c0 + 1) * CH + d0    ], acc10);
    atomicAdd(&Sb[(c0 + 1) * CH + d0 + 1], acc11);
}

// ---------------- finalize: norms, softmax, pooled, spec gate (1 block) -----
__global__ __launch_bounds__(128)
void finalize_kernel(const float* __restrict__ temperature,
                     const float* __restrict__ sp_w1,   // [16][128]
                     const float* __restrict__ sp_w2,   // [16][16]
                     const float* __restrict__ sp_w3)   // [128][16]
{
    __shared__ float nk[C], pooled[C], g1[16], g2[16];
    int tid = threadIdx.x;   // 0..127 = h*16+c
    nk[tid] = sqrtf(g_ssq_k[tid]);
    __syncthreads();

    int h = tid >> 4;
    float invq = 1.f / fmaxf(sqrtf(g_ssq_q[tid]), 1e-12f);
    float temp = temperature[h];
    int base = tid * CH;
    float l[CH];
    float m = -1e30f;
#pragma unroll
    for (int d = 0; d < CH; ++d) {
        float invk = 1.f / fmaxf(nk[h * CH + d], 1e-12f);
        l[d] = g_S[base + d] * invq * invk * temp;
        m = fmaxf(m, l[d]);
    }
    float sum = 0.f;
#pragma unroll
    for (int d = 0; d < CH; ++d) { l[d] = expf(l[d] - m); sum += l[d]; }
    float inv = 1.f / sum;
    float pl = 0.f;
#pragma unroll
    for (int d = 0; d < CH; ++d) {
        float a = l[d] * inv;
        g_attn[base + d] = a;
        pl += a * g_vsum[h * CH + d];
    }
    pooled[tid] = pl * (1.f / NPIX);
    __syncthreads();

    if (tid < 16) {
        float a = 0.f;
        for (int c = 0; c < C; ++c) a += pooled[c] * sp_w1[tid * C + c];
        g1[tid] = gelu_exact(a);
    }
    __syncthreads();
    if (tid < 16) {
        float a = 0.f;
#pragma unroll
        for (int i = 0; i < 16; ++i) a += g1[i] * sp_w2[tid * 16 + i];
        g2[tid] = gelu_exact(a);
    }
    __syncthreads();
    {
        float a = 0.f;
#pragma unroll
        for (int j = 0; j < 16; ++j) a += g2[j] * sp_w3[tid * 16 + j];
        g_spec[tid] = 1.f / (1.f + expf(-a));
    }
}

// ---------------- z = attn @ v + dwconv3x3(y)*spec --------------------------
// grid: (W/32, H/8, 8 heads), block 256
__global__ __launch_bounds__(256)
void z_kernel(const float* __restrict__ yb, const float* __restrict__ dw_w)
{
    __shared__ float vs[16][256];
    __shared__ float ys[16][10][34];
    __shared__ float attn_s[16][16];
    __shared__ float spec_s[16];
    __shared__ float dws[16][9];
    int h = blockIdx.z;
    int x0 = blockIdx.x * 32, yy0 = blockIdx.y * 8;
    int tid = threadIdx.x;
    const float* vbase = g_scratch + OFF_V + (size_t)h * CH * NPIX;
    const float* ybase = yb + (size_t)h * CH * NPIX;

    for (int i = tid; i < 16 * 256; i += 256) {
        int d = i >> 8, pp = i & 255;
        int ty = pp >> 5, tx = pp & 31;
        vs[d][pp] = vbase[(size_t)d * NPIX + (yy0 + ty) * 256 + x0 + tx];
    }
    for (int i = tid; i < 16 * 340; i += 256) {
        int cc = i / 340, rr = i % 340;
        int hy = rr / 34, hx = rr % 34;
        int gy = yy0 - 1 + hy, gx = x0 - 1 + hx;
        float v = 0.f;
        if ((unsigned)gy < 256u && (unsigned)gx < 256u)
            v = ybase[(size_t)cc * NPIX + gy * 256 + gx];
        ys[cc][hy][hx] = v;
    }
    attn_s[tid >> 4][tid & 15] = g_attn[(size_t)h * CH * CH + tid];
    if (tid < 16) spec_s[tid] = g_spec[h * CH + tid];
    for (int i = tid; i < 16 * 9; i += 256) dws[i / 9][i % 9] = dw_w[(h * CH + i / 9) * 9 + i % 9];
    __syncthreads();

    int tx = tid & 31, ty = tid >> 5;
    int n = (yy0 + ty) * 256 + x0 + tx;
    float acc[16];
#pragma unroll
    for (int cc = 0; cc < 16; ++cc) acc[cc] = 0.f;
#pragma unroll
    for (int d = 0; d < 16; ++d) {
        float vv = vs[d][tid];
#pragma unroll
        for (int cc = 0; cc < 16; ++cc) acc[cc] += attn_s[cc][d] * vv;
    }
    float* zb = g_scratch + OFF_Z + (size_t)h * CH * NPIX + n;
#pragma unroll
    for (int cc = 0; cc < 16; ++cc) {
        float dv = 0.f;
#pragma unroll
        for (int dy = 0; dy < 3; ++dy)
#pragma unroll
            for (int dx = 0; dx < 3; ++dx)
                dv += ys[cc][ty + dy][tx + dx] * dws[cc][dy * 3 + dx];
        zb[(size_t)cc * NPIX] = acc[cc] + spec_s[cc] * dv;
    }
}

// ---------------- launch: full pipeline per batch ---------------------------
extern "C" void kernel_launch(void* const* d_in, const int* in_sizes, int n_in,
                              void* d_out, int out_size)
{
    const float* x           = (const float*)d_in[0];
    const float* y           = (const float*)d_in[1];
    const float* qkv_w       = (const float*)d_in[2];
    const float* qkv_dw_w    = (const float*)d_in[3];
    const float* proj_w      = (const float*)d_in[4];
    const float* sa_w1       = (const float*)d_in[5];
    const float* sa_w2       = (const float*)d_in[6];
    const float* sa_w3       = (const float*)d_in[7];
    const float* sp_w1       = (const float*)d_in[8];
    const float* sp_w2       = (const float*)d_in[9];
    const float* sp_w3       = (const float*)d_in[10];
    const float* dw_w        = (const float*)d_in[11];
    const float* temperature = (const float*)d_in[12];
    float* out = (float*)d_out;

    for (int b = 0; b < 2; ++b) {
        const float* xb = x + (size_t)b * C * NPIX;
        const float* yb = y + (size_t)b * C * NPIX;
        float* outb = out + (size_t)b * C * NPIX;

        init_kernel<<<1, 256>>>();
        sa_kernel<<<NPIX / 256, 256>>>(yb, sa_w1, sa_w2, sa_w3);
        qkv_conv_kernel<<<dim3(NPIX / 128, C3 / 64), 256>>>(qkv_w, xb);
        dw_split_kernel<<<dim3(WIMG / 32, HIMG / 8, C3), 256>>>(qkv_dw_w);
        gram_kernel<<<dim3(16, HD), 256>>>();
        finalize_kernel<<<1, 128>>>(temperature, sp_w1, sp_w2, sp_w3);
        z_kernel<<<dim3(WIMG / 32, HIMG / 8, HD), 256>>>(yb, dw_w);
        proj_conv_kernel<<<dim3(NPIX / 128, C / 64), 256>>>(proj_w, outb);
    }
}

// round 6
// speedup vs baseline: 1.2115x; 1.2115x over previous
#include <cuda_runtime.h>
#include <math.h>

#define DEVFN __device__ __forceinline__
typedef unsigned long long ull;

constexpr int C    = 128;
constexpr int C3   = 384;
constexpr int HIMG = 256;
constexpr int WIMG = 256;
constexpr int NPIX = HIMG * WIMG;   // 65536
constexpr int HD   = 8;
constexpr int CH   = 16;            // channels per head

// ---------------- scratch arena (single batch at a time) --------------------
constexpr size_t OFF_QKV  = 0;
constexpr size_t OFF_QKVD = (size_t)C3 * NPIX;
constexpr size_t OFF_Q    = OFF_QKVD;
constexpr size_t OFF_K    = OFF_QKVD + (size_t)C * NPIX;
constexpr size_t OFF_V    = OFF_QKVD + (size_t)2 * C * NPIX;
constexpr size_t OFF_Z    = 0;   // aliases qkv region (dead after dw_split)

__device__ float g_scratch[(size_t)2 * C3 * NPIX];   // 201.3 MB
__device__ float g_sa[NPIX];
__device__ float g_ssq_q[C];
__device__ float g_ssq_k[C];
__device__ float g_vsum[C];
__device__ float g_S[HD * CH * CH];
__device__ float g_attn[HD * CH * CH];
__device__ float g_spec[C];

// ---------------- f32x2 packed-FMA helpers (Blackwell FFMA2) ----------------
DEVFN ull dup2(float v) {
    ull r;
    asm("mov.b64 %0, {%1, %1};" : "=l"(r) : "f"(v));
    return r;
}
DEVFN void fma2(ull &c, ull a, ull b) {
    asm("fma.rn.f32x2 %0, %1, %2, %0;" : "+l"(c) : "l"(a), "l"(b));
}
DEVFN void upk2(ull v, float &lo, float &hi) {
    asm("mov.b64 {%0, %1}, %2;" : "=f"(lo), "=f"(hi) : "l"(v));
}

DEVFN float gelu_exact(float x) {
    return 0.5f * x * (1.0f + erff(x * 0.70710678118654752440f));
}

// ---------------- init ------------------------------------------------------
__global__ void init_kernel() {
    int tid = threadIdx.x;
    for (int i = tid; i < C; i += 256) { g_ssq_q[i] = 0.f; g_ssq_k[i] = 0.f; g_vsum[i] = 0.f; }
    for (int i = tid; i < HD * CH * CH; i += 256) g_S[i] = 0.f;
}

// ---------------- spatial-attention gate: sa[n] from y[b] -------------------
__global__ __launch_bounds__(256)
void sa_kernel(const float* __restrict__ yb,
               const float* __restrict__ w1,   // [16][128]
               const float* __restrict__ w2,   // [16][16]
               const float* __restrict__ w3)   // [16]
{
    __shared__ float w1s[16][128];
    __shared__ float w2s[16][16];
    __shared__ float w3s[16];
    int tid = threadIdx.x;
    for (int i = tid; i < 16 * 128; i += 256) w1s[i >> 7][i & 127] = w1[i];
    w2s[tid >> 4][tid & 15] = w2[tid];
    if (tid < 16) w3s[tid] = w3[tid];
    __syncthreads();

    int n = blockIdx.x * 256 + tid;
    const float* yp = yb + n;

    float t1[16];
#pragma unroll
    for (int j = 0; j < 16; ++j) t1[j] = 0.f;
    for (int ic = 0; ic < C; ic += 4) {
        float y0 = yp[(size_t)(ic + 0) * NPIX];
        float y1 = yp[(size_t)(ic + 1) * NPIX];
        float y2 = yp[(size_t)(ic + 2) * NPIX];
        float y3 = yp[(size_t)(ic + 3) * NPIX];
#pragma unroll
        for (int j = 0; j < 16; ++j)
            t1[j] += w1s[j][ic] * y0 + w1s[j][ic + 1] * y1
                   + w1s[j][ic + 2] * y2 + w1s[j][ic + 3] * y3;
    }
    float t2[16];
#pragma unroll
    for (int j = 0; j < 16; ++j) {
        float a = 0.f;
#pragma unroll
        for (int i = 0; i < 16; ++i) a += fmaxf(t1[i], 0.f) * w2s[j][i];
        t2[j] = fmaxf(a, 0.f);
    }
    float s3 = 0.f;
#pragma unroll
    for (int i = 0; i < 16; ++i) s3 += t2[i] * w3s[i];
    g_sa[n] = 1.f / (1.f + expf(-s3));
}

// ---------------- conv1x1 GEMM: OUT[oc,n] = sum_ic W[oc,ic]*X[ic,n] ---------
DEVFN void conv1x1_body(const float* __restrict__ Wt,
                        const float* __restrict__ X,
                        float* __restrict__ OUT)
{
    __shared__ __align__(16) float xs[16][128];
    __shared__ __align__(16) float ws[16][66];
    const int tid    = threadIdx.x;
    const int nbase  = blockIdx.x * 128;
    const int ocbase = blockIdx.y * 64;
    const int lane = tid & 31;
    const int wrp  = tid >> 5;
    const int n0   = lane * 4;
    const int oc0  = wrp * 8;

    ull acc[4][4];
#pragma unroll
    for (int i = 0; i < 4; ++i)
#pragma unroll
        for (int j = 0; j < 4; ++j) acc[i][j] = 0ull;

    const float* Xb = X + nbase;
    for (int ic0 = 0; ic0 < C; ic0 += 16) {
#pragma unroll
        for (int i = 0; i < 2; ++i) {
            int idx = tid + i * 256;
            int r = idx >> 5, c4 = (idx & 31) << 2;
            *(float4*)&xs[r][c4] =
                *(const float4*)&Xb[(size_t)(ic0 + r) * NPIX + c4];
        }
        {
            int oc = tid >> 2, kk0 = (tid & 3) << 2;
            float4 wv = *(const float4*)&Wt[(size_t)(ocbase + oc) * C + ic0 + kk0];
            ws[kk0 + 0][oc] = wv.x;
            ws[kk0 + 1][oc] = wv.y;
            ws[kk0 + 2][oc] = wv.z;
            ws[kk0 + 3][oc] = wv.w;
        }
        __syncthreads();
#pragma unroll
        for (int kk = 0; kk < 16; ++kk) {
            float4 xv = *(const float4*)&xs[kk][n0];
            ull xd[4];
            xd[0] = dup2(xv.x); xd[1] = dup2(xv.y);
            xd[2] = dup2(xv.z); xd[3] = dup2(xv.w);
            ull wp[4];
#pragma unroll
            for (int i = 0; i < 4; ++i)
                wp[i] = *(const ull*)&ws[kk][oc0 + 2 * i];
#pragma unroll
            for (int i = 0; i < 4; ++i)
#pragma unroll
                for (int j = 0; j < 4; ++j)
                    fma2(acc[i][j], wp[i], xd[j]);
        }
        __syncthreads();
    }
    float* Ob = OUT + nbase;
#pragma unroll
    for (int i = 0; i < 4; ++i) {
        float lo[4], hi[4];
#pragma unroll
        for (int j = 0; j < 4; ++j) upk2(acc[i][j], lo[j], hi[j]);
        *(float4*)&Ob[(size_t)(ocbase + oc0 + 2 * i) * NPIX + n0] =
            make_float4(lo[0], lo[1], lo[2], lo[3]);
        *(float4*)&Ob[(size_t)(ocbase + oc0 + 2 * i + 1) * NPIX + n0] =
            make_float4(hi[0], hi[1], hi[2], hi[3]);
    }
}

__global__ __launch_bounds__(256, 4)
void qkv_conv_kernel(const float* __restrict__ Wt, const float* __restrict__ X) {
    conv1x1_body(Wt, X, g_scratch + OFF_QKV);
}
__global__ __launch_bounds__(256, 4)
void proj_conv_kernel(const float* __restrict__ Wt, float* __restrict__ OUT) {
    conv1x1_body(Wt, g_scratch + OFF_Z, OUT);
}

// ---------------- dwconv3x3 + split + gate + reductions ---------------------
// 4 pixels/thread: block tile 128x8, grid (2, 32, C3)
// Interior at smem cols 4..131 (16B-aligned float4 stores/loads); halos at
// cols 3 and 132 via scalar stores (no alignment requirement).
__global__ __launch_bounds__(256)
void dw_split_kernel(const float* __restrict__ qkv_dw_w)
{
    __shared__ __align__(16) float s[10][136];
    __shared__ float red[8];
    int ch = blockIdx.z;
    int x0 = blockIdx.x * 128, y0 = blockIdx.y * 8;
    int tid = threadIdx.x;
    const float* src = g_scratch + OFF_QKV + (size_t)ch * NPIX;

    // halo fill: 10 rows x (32 aligned float4 + 2 edge scalars)
    for (int i = tid; i < 330; i += 256) {
        int row = i / 33, seg = i - row * 33;
        int gy = y0 - 1 + row;
        bool yok = (unsigned)gy < 256u;
        if (seg < 32) {
            float4 v = make_float4(0.f, 0.f, 0.f, 0.f);
            if (yok) v = *(const float4*)&src[gy * 256 + x0 + seg * 4];
            *(float4*)&s[row][4 + seg * 4] = v;     // byte off 16+16*seg: aligned
        } else {
            float l = 0.f, r = 0.f;
            if (yok) {
                if (x0 > 0)         l = src[gy * 256 + x0 - 1];
                if (x0 + 128 < 256) r = src[gy * 256 + x0 + 128];
            }
            s[row][3]   = l;
            s[row][132] = r;
        }
    }
    float w0 = qkv_dw_w[ch * 9 + 0], w1 = qkv_dw_w[ch * 9 + 1], w2 = qkv_dw_w[ch * 9 + 2];
    float w3 = qkv_dw_w[ch * 9 + 3], w4 = qkv_dw_w[ch * 9 + 4], w5 = qkv_dw_w[ch * 9 + 5];
    float w6 = qkv_dw_w[ch * 9 + 6], w7 = qkv_dw_w[ch * 9 + 7], w8 = qkv_dw_w[ch * 9 + 8];
    __syncthreads();

    int tx = tid & 31, ty = tid >> 5;
    int cb = 4 + 4 * tx;               // smem col of first output pixel (aligned)
    float4 m0 = *(float4*)&s[ty    ][cb];
    float  l0 = s[ty    ][cb - 1],  e0 = s[ty    ][cb + 4];
    float4 m1 = *(float4*)&s[ty + 1][cb];
    float  l1 = s[ty + 1][cb - 1],  e1 = s[ty + 1][cb + 4];
    float4 m2 = *(float4*)&s[ty + 2][cb];
    float  l2 = s[ty + 2][cb - 1],  e2 = s[ty + 2][cb + 4];
    float c0[6] = {l0, m0.x, m0.y, m0.z, m0.w, e0};
    float c1[6] = {l1, m1.x, m1.y, m1.z, m1.w, e1};
    float c2[6] = {l2, m2.x, m2.y, m2.z, m2.w, e2};

    float a[4];
#pragma unroll
    for (int j = 0; j < 4; ++j) {
        a[j] = w0 * c0[j] + w1 * c0[j + 1] + w2 * c0[j + 2]
             + w3 * c1[j] + w4 * c1[j + 1] + w5 * c1[j + 2]
             + w6 * c2[j] + w7 * c2[j + 1] + w8 * c2[j + 2];
    }

    int n = (y0 + ty) * 256 + x0 + 4 * tx;
    float contrib;
    float* tgt;
    if (ch < C) {
        float4 sa4 = *(const float4*)&g_sa[n];
        a[0] *= sa4.x; a[1] *= sa4.y; a[2] *= sa4.z; a[3] *= sa4.w;
        *(float4*)&g_scratch[OFF_Q + (size_t)ch * NPIX + n] = make_float4(a[0], a[1], a[2], a[3]);
        contrib = a[0]*a[0] + a[1]*a[1] + a[2]*a[2] + a[3]*a[3];
        tgt = &g_ssq_q[ch];
    } else if (ch < 2 * C) {
        int c = ch - C;
        *(float4*)&g_scratch[OFF_K + (size_t)c * NPIX + n] = make_float4(a[0], a[1], a[2], a[3]);
        contrib = a[0]*a[0] + a[1]*a[1] + a[2]*a[2] + a[3]*a[3];
        tgt = &g_ssq_k[c];
    } else {
        int c = ch - 2 * C;
        *(float4*)&g_scratch[OFF_V + (size_t)c * NPIX + n] = make_float4(a[0], a[1], a[2], a[3]);
        contrib = a[0] + a[1] + a[2] + a[3];
        tgt = &g_vsum[c];
    }

    for (int o = 16; o; o >>= 1) contrib += __shfl_xor_sync(0xffffffffu, contrib, o);
    if ((tid & 31) == 0) red[tid >> 5] = contrib;
    __syncthreads();
    if (tid == 0) {
        float t = 0.f;
#pragma unroll
        for (int i = 0; i < 8; ++i) t += red[i];
        atomicAdd(tgt, t);
    }
}

// ---------------- Gram: S[h,c,d] = sum_n q[c,n]*k[d,n]  (f32x2 core) --------
__global__ __launch_bounds__(256)
void gram_kernel()
{
    __shared__ __align__(16) float qs[16][258];
    __shared__ __align__(16) float ks[16][258];
    int h = blockIdx.y;
    const float* qb = g_scratch + OFF_Q + (size_t)h * CH * NPIX;
    const float* kb = g_scratch + OFF_K + (size_t)h * CH * NPIX;
    int n0 = blockIdx.x * 4096;
    int tid = threadIdx.x;
    int slice = tid >> 6;          // 0..3
    int r = tid & 63;
    int c0 = (r >> 3) * 2;
    int d0 = (r & 7) * 2;
    ull a00 = 0ull, a01 = 0ull, a10 = 0ull, a11 = 0ull;

    for (int it = 0; it < 16; ++it) {
        int nb = n0 + it * 256;
        for (int i = tid; i < 16 * 256; i += 256) {
            int rr = i >> 8, cc = i & 255;
            qs[rr][cc] = qb[(size_t)rr * NPIX + nb + cc];
            ks[rr][cc] = kb[(size_t)rr * NPIX + nb + cc];
        }
        __syncthreads();
        int base = slice * 64;
        const ull* q0p = (const ull*)&qs[c0    ][base];
        const ull* q1p = (const ull*)&qs[c0 + 1][base];
        const ull* k0p = (const ull*)&ks[d0    ][base];
        const ull* k1p = (const ull*)&ks[d0 + 1][base];
#pragma unroll 8
        for (int nn = 0; nn < 32; ++nn) {
            ull q0 = q0p[nn], q1 = q1p[nn];
            ull k0 = k0p[nn], k1 = k1p[nn];
            fma2(a00, q0, k0); fma2(a01, q0, k1);
            fma2(a10, q1, k0); fma2(a11, q1, k1);
        }
        __syncthreads();
    }
    float lo, hi;
    float* Sb = g_S + (size_t)h * CH * CH;
    upk2(a00, lo, hi); atomicAdd(&Sb[(c0    ) * CH + d0    ], lo + hi);
    upk2(a01, lo, hi); atomicAdd(&Sb[(c0    ) * CH + d0 + 1], lo + hi);
    upk2(a10, lo, hi); atomicAdd(&Sb[(c0 + 1) * CH + d0    ], lo + hi);
    upk2(a11, lo, hi); atomicAdd(&Sb[(c0 + 1) * CH + d0 + 1], lo + hi);
}

// ---------------- finalize: norms, softmax, pooled, spec gate (1 block) -----
__global__ __launch_bounds__(128)
void finalize_kernel(const float* __restrict__ temperature,
                     const float* __restrict__ sp_w1,
                     const float* __restrict__ sp_w2,
                     const float* __restrict__ sp_w3)
{
    __shared__ float nk[C], pooled[C], g1[16], g2[16];
    int tid = threadIdx.x;   // 0..127 = h*16+c
    nk[tid] = sqrtf(g_ssq_k[tid]);
    __syncthreads();

    int h = tid >> 4;
    float invq = 1.f / fmaxf(sqrtf(g_ssq_q[tid]), 1e-12f);
    float temp = temperature[h];
    int base = tid * CH;
    float l[CH];
    float m = -1e30f;
#pragma unroll
    for (int d = 0; d < CH; ++d) {
        float invk = 1.f / fmaxf(nk[h * CH + d], 1e-12f);
        l[d] = g_S[base + d] * invq * invk * temp;
        m = fmaxf(m, l[d]);
    }
    float sum = 0.f;
#pragma unroll
    for (int d = 0; d < CH; ++d) { l[d] = expf(l[d] - m); sum += l[d]; }
    float inv = 1.f / sum;
    float pl = 0.f;
#pragma unroll
    for (int d = 0; d < CH; ++d) {
        float a = l[d] * inv;
        g_attn[base + d] = a;
        pl += a * g_vsum[h * CH + d];
    }
    pooled[tid] = pl * (1.f / NPIX);
    __syncthreads();

    if (tid < 16) {
        float a = 0.f;
        for (int c = 0; c < C; ++c) a += pooled[c] * sp_w1[tid * C + c];
        g1[tid] = gelu_exact(a);
    }
    __syncthreads();
    if (tid < 16) {
        float a = 0.f;
#pragma unroll
        for (int i = 0; i < 16; ++i) a += g1[i] * sp_w2[tid * 16 + i];
        g2[tid] = gelu_exact(a);
    }
    __syncthreads();
    {
        float a = 0.f;
#pragma unroll
        for (int j = 0; j < 16; ++j) a += g2[j] * sp_w3[tid * 16 + j];
        g_spec[tid] = 1.f / (1.f + expf(-a));
    }
}

// ---------------- z = attn @ v + dwconv3x3(y)*spec --------------------------
__global__ __launch_bounds__(256)
void z_kernel(const float* __restrict__ yb, const float* __restrict__ dw_w)
{
    __shared__ float vs[16][256];
    __shared__ float ys[16][10][34];
    __shared__ float attn_s[16][16];
    __shared__ float spec_s[16];
    __shared__ float dws[16][9];
    int h = blockIdx.z;
    int x0 = blockIdx.x * 32, yy0 = blockIdx.y * 8;
    int tid = threadIdx.x;
    const float* vbase = g_scratch + OFF_V + (size_t)h * CH * NPIX;
    const float* ybase = yb + (size_t)h * CH * NPIX;

    for (int i = tid; i < 16 * 256; i += 256) {
        int d = i >> 8, pp = i & 255;
        int ty = pp >> 5, tx = pp & 31;
        vs[d][pp] = vbase[(size_t)d * NPIX + (yy0 + ty) * 256 + x0 + tx];
    }
    for (int i = tid; i < 16 * 340; i += 256) {
        int cc = i / 340, rr = i % 340;
        int hy = rr / 34, hx = rr % 34;
        int gy = yy0 - 1 + hy, gx = x0 - 1 + hx;
        float v = 0.f;
        if ((unsigned)gy < 256u && (unsigned)gx < 256u)
            v = ybase[(size_t)cc * NPIX + gy * 256 + gx];
        ys[cc][hy][hx] = v;
    }
    attn_s[tid >> 4][tid & 15] = g_attn[(size_t)h * CH * CH + tid];
    if (tid < 16) spec_s[tid] = g_spec[h * CH + tid];
    for (int i = tid; i < 16 * 9; i += 256) dws[i / 9][i % 9] = dw_w[(h * CH + i / 9) * 9 + i % 9];
    __syncthreads();

    int tx = tid & 31, ty = tid >> 5;
    int n = (yy0 + ty) * 256 + x0 + tx;
    float acc[16];
#pragma unroll
    for (int cc = 0; cc < 16; ++cc) acc[cc] = 0.f;
#pragma unroll
    for (int d = 0; d < 16; ++d) {
        float vv = vs[d][tid];
#pragma unroll
        for (int cc = 0; cc < 16; ++cc) acc[cc] += attn_s[cc][d] * vv;
    }
    float* zb = g_scratch + OFF_Z + (size_t)h * CH * NPIX + n;
#pragma unroll
    for (int cc = 0; cc < 16; ++cc) {
        float dv = 0.f;
#pragma unroll
        for (int dy = 0; dy < 3; ++dy)
#pragma unroll
            for (int dx = 0; dx < 3; ++dx)
                dv += ys[cc][ty + dy][tx + dx] * dws[cc][dy * 3 + dx];
        zb[(size_t)cc * NPIX] = acc[cc] + spec_s[cc] * dv;
    }
}

// ---------------- launch: full pipeline per batch ---------------------------
extern "C" void kernel_launch(void* const* d_in, const int* in_sizes, int n_in,
                              void* d_out, int out_size)
{
    const float* x           = (const float*)d_in[0];
    const float* y           = (const float*)d_in[1];
    const float* qkv_w       = (const float*)d_in[2];
    const float* qkv_dw_w    = (const float*)d_in[3];
    const float* proj_w      = (const float*)d_in[4];
    const float* sa_w1       = (const float*)d_in[5];
    const float* sa_w2       = (const float*)d_in[6];
    const float* sa_w3       = (const float*)d_in[7];
    const float* sp_w1       = (const float*)d_in[8];
    const float* sp_w2       = (const float*)d_in[9];
    const float* sp_w3       = (const float*)d_in[10];
    const float* dw_w        = (const float*)d_in[11];
    const float* temperature = (const float*)d_in[12];
    float* out = (float*)d_out;

    for (int b = 0; b < 2; ++b) {
        const float* xb = x + (size_t)b * C * NPIX;
        const float* yb = y + (size_t)b * C * NPIX;
        float* outb = out + (size_t)b * C * NPIX;

        init_kernel<<<1, 256>>>();
        sa_kernel<<<NPIX / 256, 256>>>(yb, sa_w1, sa_w2, sa_w3);
        qkv_conv_kernel<<<dim3(NPIX / 128, C3 / 64), 256>>>(qkv_w, xb);
        dw_split_kernel<<<dim3(WIMG / 128, HIMG / 8, C3), 256>>>(qkv_dw_w);
        gram_kernel<<<dim3(16, HD), 256>>>();
        finalize_kernel<<<1, 128>>>(temperature, sp_w1, sp_w2, sp_w3);
        z_kernel<<<dim3(WIMG / 32, HIMG / 8, HD), 256>>>(yb, dw_w);
        proj_conv_kernel<<<dim3(NPIX / 128, C / 64), 256>>>(proj_w, outb);
    }
}